// round 14
// baseline (speedup 1.0000x reference)
#include <cuda_runtime.h>
#include <cuda_bf16.h>
#include <cuda_fp16.h>
#include <math.h>
#include <stdint.h>

#define B_  2
#define L_  2048
#define E_  1024
#define H_  16
#define HD_ 64
#define M_  (B_ * L_)   // 4096

// ---------------------------------------------------------------------------
// Scratch (fp16 world)
// ---------------------------------------------------------------------------
__device__ __align__(16) __half g_x16[M_ * E_];
__device__ __align__(16) __half g_wqkv16[3 * E_ * E_];
__device__ __align__(16) __half g_wo16[E_ * E_];
__device__ __align__(16) __half g_q16[M_ * E_];
__device__ __align__(16) __half g_k16[M_ * E_];
__device__ __align__(16) __half g_v16[M_ * E_];
__device__ __align__(16) __half g_a16[M_ * E_];

// ---------------------------------------------------------------------------
// helpers
// ---------------------------------------------------------------------------
__device__ __forceinline__ uint32_t smem_to_u32(const void* p) {
    uint32_t a;
    asm("{ .reg .u64 t; cvta.to.shared.u64 t, %1; cvt.u32.u64 %0, t; }" : "=r"(a) : "l"(p));
    return a;
}
__device__ __forceinline__ void cp_async16(uint32_t dst, const void* src) {
    asm volatile("cp.async.cg.shared.global [%0], [%1], 16;" :: "r"(dst), "l"(src));
}
#define CP_COMMIT() asm volatile("cp.async.commit_group;")
#define CP_WAIT2()  asm volatile("cp.async.wait_group 2;")
#define CP_WAIT1()  asm volatile("cp.async.wait_group 1;")
#define CP_WAIT0()  asm volatile("cp.async.wait_group 0;")

__device__ __forceinline__ void ldmatrix_x4(
    uint32_t& r0, uint32_t& r1, uint32_t& r2, uint32_t& r3, uint32_t addr)
{
    asm volatile("ldmatrix.sync.aligned.m8n8.x4.shared.b16 {%0,%1,%2,%3}, [%4];"
        : "=r"(r0), "=r"(r1), "=r"(r2), "=r"(r3) : "r"(addr));
}
__device__ __forceinline__ void ldmatrix_x4_trans(
    uint32_t& r0, uint32_t& r1, uint32_t& r2, uint32_t& r3, uint32_t addr)
{
    asm volatile("ldmatrix.sync.aligned.m8n8.x4.trans.shared.b16 {%0,%1,%2,%3}, [%4];"
        : "=r"(r0), "=r"(r1), "=r"(r2), "=r"(r3) : "r"(addr));
}
__device__ __forceinline__ void mma_f16(
    float& c0, float& c1, float& c2, float& c3,
    uint32_t a0, uint32_t a1, uint32_t a2, uint32_t a3, uint32_t b0, uint32_t b1)
{
    asm volatile(
        "mma.sync.aligned.m16n8k16.row.col.f32.f16.f16.f32 "
        "{%0,%1,%2,%3}, {%4,%5,%6,%7}, {%8,%9}, {%0,%1,%2,%3};"
        : "+f"(c0), "+f"(c1), "+f"(c2), "+f"(c3)
        : "r"(a0), "r"(a1), "r"(a2), "r"(a3), "r"(b0), "r"(b1));
}
__device__ __forceinline__ uint32_t pack_h2(float a, float b) {
    __half2 p = __floats2half2_rn(a, b);
    return *(uint32_t*)&p;
}

// ---------------------------------------------------------------------------
// Fused prepass: fp32 -> fp16 for x, Wqkv, Wout in one launch
// ---------------------------------------------------------------------------
#define NX4  (M_ * E_ / 4)
#define NWQ4 (3 * E_ * E_ / 4)
#define NWO4 (E_ * E_ / 4)
#define NALL4 (NX4 + NWQ4 + NWO4)

__global__ void conv_all(const float4* __restrict__ x,
                         const float4* __restrict__ wq,
                         const float4* __restrict__ wo,
                         __half2* __restrict__ x16,
                         __half2* __restrict__ wq16,
                         __half2* __restrict__ wo16)
{
    int i = blockIdx.x * blockDim.x + threadIdx.x;
    if (i >= NALL4) return;
    const float4* src;
    __half2* dst;
    int j;
    if (i < NX4)             { src = x;  dst = x16;  j = i; }
    else if (i < NX4 + NWQ4) { src = wq; dst = wq16; j = i - NX4; }
    else                     { src = wo; dst = wo16; j = i - NX4 - NWQ4; }
    float4 t = src[j];
    dst[2*j]   = __floats2half2_rn(t.x, t.y);
    dst[2*j+1] = __floats2half2_rn(t.z, t.w);
}

// ---------------------------------------------------------------------------
// GEMM: C = A16 @ W16^T (+bias), 1 fp16 MMA per atom. BK=32, 3-stage pipeline.
// BM=128, BN=128; 256 threads, 8 warps (warp tile 64x32). stride-40 rows.
// ---------------------------------------------------------------------------
#define GT_STRIDE 40
#define GT_TILE   (128 * GT_STRIDE * 2)   // 10240 B
#define GT_STAGE  (2 * GT_TILE)           // 20480 B (A, W)
#define GEMM_SMEM (3 * GT_STAGE)          // 61440 B

template<int EPI>
__global__ __launch_bounds__(256, 2) void gemm_tc(
    const __half* __restrict__ A16, const __half* __restrict__ W16,
    const float* __restrict__ bias, float* __restrict__ Cf,
    __half* __restrict__ q16, __half* __restrict__ k16, __half* __restrict__ v16,
    int M, int N, int K)
{
    extern __shared__ char smg[];
    const uint32_t sbase = smem_to_u32(smg);

    const int bm   = blockIdx.y * 128;
    const int bn   = blockIdx.x * 128;
    const int tid  = threadIdx.x;
    const int wid  = tid >> 5;
    const int lane = tid & 31;
    const int wm   = wid >> 2;
    const int wn   = wid & 3;

    float c[4][4][4];
#pragma unroll
    for (int i = 0; i < 4; i++)
#pragma unroll
        for (int j = 0; j < 4; j++)
#pragma unroll
            for (int r = 0; r < 4; r++) c[i][j][r] = 0.f;

    auto load_stage = [&](int s, int k0) {
        const uint32_t base = sbase + s * GT_STAGE;
        const __half* srcA = A16 + (size_t)bm * K + k0;
        const __half* srcW = W16 + (size_t)bn * K + k0;
#pragma unroll
        for (int i = 0; i < 2; i++) {
            int chunk = tid * 2 + i;
            int row   = chunk >> 2;
            int cc    = chunk & 3;
            uint32_t doff = row * (GT_STRIDE * 2) + cc * 16;
            cp_async16(base + doff,           srcA + (size_t)row * K + cc * 8);
            cp_async16(base + GT_TILE + doff, srcW + (size_t)row * K + cc * 8);
        }
    };

    const int niter = K / 32;
    load_stage(0, 0);
    CP_COMMIT();
    load_stage(1, 32);
    CP_COMMIT();

    for (int it = 0; it < niter; it++) {
        if (it + 2 < niter) { load_stage((it + 2) % 3, (it + 2) * 32); CP_COMMIT(); CP_WAIT2(); }
        else if (it + 1 < niter) { CP_WAIT1(); }
        else                     { CP_WAIT0(); }
        __syncthreads();

        const uint32_t stage = sbase + (it % 3) * GT_STAGE;
#pragma unroll
        for (int ks = 0; ks < 2; ks++) {
            const int kof = ks * 16;
            uint32_t af[4][4], bfr[4][2];
#pragma unroll
            for (int i = 0; i < 4; i++) {
                int m0 = wm * 64 + i * 16;
                uint32_t ad = stage +
                    (uint32_t)((m0 + (lane & 15)) * GT_STRIDE + kof + (lane >> 4) * 8) * 2;
                ldmatrix_x4(af[i][0], af[i][1], af[i][2], af[i][3], ad);
            }
#pragma unroll
            for (int jp = 0; jp < 2; jp++) {
                int n0 = wn * 32 + jp * 16;
                int nrow = n0 + ((lane >> 4) << 3) + (lane & 7);
                int bk   = kof + (((lane >> 3) & 1) << 3);
                uint32_t bd = stage + GT_TILE + (uint32_t)(nrow * GT_STRIDE + bk) * 2;
                ldmatrix_x4(bfr[jp*2][0], bfr[jp*2][1], bfr[jp*2+1][0], bfr[jp*2+1][1], bd);
            }
#pragma unroll
            for (int i = 0; i < 4; i++)
#pragma unroll
                for (int j = 0; j < 4; j++)
                    mma_f16(c[i][j][0], c[i][j][1], c[i][j][2], c[i][j][3],
                            af[i][0], af[i][1], af[i][2], af[i][3],
                            bfr[j][0], bfr[j][1]);
        }
        __syncthreads();
    }

    // ---- epilogue ----
    const int g4 = lane >> 2;
    const int t4 = lane & 3;
    if (EPI == 0) {
#pragma unroll
        for (int i = 0; i < 4; i++) {
            int row0 = bm + wm * 64 + i * 16 + g4;
#pragma unroll
            for (int j = 0; j < 4; j++) {
                int col = bn + wn * 32 + j * 8 + t4 * 2;
                float bx = bias[col], by = bias[col + 1];
                *(float2*)(Cf + (size_t)row0 * N + col) =
                    make_float2(c[i][j][0] + bx, c[i][j][1] + by);
                *(float2*)(Cf + (size_t)(row0 + 8) * N + col) =
                    make_float2(c[i][j][2] + bx, c[i][j][3] + by);
            }
        }
    } else {
        const int seg     = bn >> 10;          // 0=Q, 1=K, 2=V
        const int segbase = bn & 1023;
#pragma unroll
        for (int i = 0; i < 4; i++) {
            int row0 = bm + wm * 64 + i * 16 + g4;
#pragma unroll
            for (int j = 0; j < 4; j++) {
                int colg = bn + wn * 32 + j * 8 + t4 * 2;
                int cols = segbase + wn * 32 + j * 8 + t4 * 2;
                float bx = bias[colg], by = bias[colg + 1];
                float v0 = c[i][j][0] + bx, v1 = c[i][j][1] + by;
                float v2 = c[i][j][2] + bx, v3 = c[i][j][3] + by;
                size_t i0 = (size_t)row0 * E_ + cols;
                size_t i1 = (size_t)(row0 + 8) * E_ + cols;
                if (seg == 0) {
                    *(__half2*)(q16 + i0) = __floats2half2_rn(v0 * 0.125f, v1 * 0.125f);
                    *(__half2*)(q16 + i1) = __floats2half2_rn(v2 * 0.125f, v3 * 0.125f);
                } else if (seg == 1) {
                    *(__half2*)(k16 + i0) = __floats2half2_rn(v0, v1);
                    *(__half2*)(k16 + i1) = __floats2half2_rn(v2, v3);
                } else {
                    *(__half2*)(v16 + i0) = __floats2half2_rn(v0, v1);
                    *(__half2*)(v16 + i1) = __floats2half2_rn(v2, v3);
                }
            }
        }
    }
}

// ---------------------------------------------------------------------------
// Flash attention: S = Q16 @ K16^T (1 mma); O += P16 @ V16 (1 mma).
// Block: (b, h, 128 q-rows). K-tiles of 64. 3-stage cp.async pipeline.
// ---------------------------------------------------------------------------
#define AT_STRIDE 72
#define AT_TILE   (64 * AT_STRIDE * 2)     // 9216
#define AT_STAGE  (2 * AT_TILE)            // 18432 (K16, V16)
#define ATTN_SMEM (3 * AT_STAGE)           // 55296

__global__ __launch_bounds__(256, 2) void attention_tc(
    const __half* __restrict__ q16,
    const __half* __restrict__ k16, const __half* __restrict__ v16,
    __half* __restrict__ a16)
{
    extern __shared__ char sma[];
    const uint32_t sbase = smem_to_u32(sma);

    const int q0   = blockIdx.x * 128;
    const int h    = blockIdx.y;
    const int b    = blockIdx.z;
    const int tid  = threadIdx.x;
    const int wid  = tid >> 5;
    const int lane = tid & 31;
    const int basecol = h * HD_;

    // ---- Q fragments directly from global (ldmatrix A-frag layout) ----
    uint32_t qf[4][4];
    {
        const int r0 = b * L_ + q0 + wid * 16 + (lane >> 2);
        const int c0 = basecol + (lane & 3) * 2;
#pragma unroll
        for (int ks = 0; ks < 4; ks++) {
            size_t i00 = (size_t)r0 * E_ + c0 + ks * 16;
            qf[ks][0] = *(const uint32_t*)(q16 + i00);
            qf[ks][1] = *(const uint32_t*)(q16 + i00 + 8 * E_);
            qf[ks][2] = *(const uint32_t*)(q16 + i00 + 8);
            qf[ks][3] = *(const uint32_t*)(q16 + i00 + 8 * E_ + 8);
        }
    }

    auto load_kv = [&](int s, int kt) {
        const uint32_t base = sbase + s * AT_STAGE;
        const int rowg = b * L_ + kt;
#pragma unroll
        for (int i = 0; i < 2; i++) {
            int chunk = tid * 2 + i;        // 0..511
            int row   = chunk >> 3;
            int cc    = chunk & 7;
            size_t src = (size_t)(rowg + row) * E_ + basecol + cc * 8;
            uint32_t doff = row * (AT_STRIDE * 2) + cc * 16;
            cp_async16(base + doff,           k16 + src);
            cp_async16(base + AT_TILE + doff, v16 + src);
        }
    };

    const int NTILE = L_ / 64;
    load_kv(0, 0);
    CP_COMMIT();
    load_kv(1, 64);
    CP_COMMIT();

    float o[8][4];
#pragma unroll
    for (int j = 0; j < 8; j++)
#pragma unroll
        for (int r = 0; r < 4; r++) o[j][r] = 0.f;
    float m0 = -1e30f, m1 = -1e30f, l0 = 0.f, l1 = 0.f;

    for (int it = 0; it < NTILE; it++) {
        if (it + 2 < NTILE) { load_kv((it + 2) % 3, (it + 2) * 64); CP_COMMIT(); CP_WAIT2(); }
        else if (it + 1 < NTILE) { CP_WAIT1(); }
        else                     { CP_WAIT0(); }
        __syncthreads();

        const uint32_t stage = sbase + (it % 3) * AT_STAGE;

        // ---- S = Q @ K^T, fp16 ----
        float s[8][4];
#pragma unroll
        for (int j = 0; j < 8; j++)
#pragma unroll
            for (int r = 0; r < 4; r++) s[j][r] = 0.f;

#pragma unroll
        for (int ks = 0; ks < 4; ks++) {
            const int kof = ks * 16;
            uint32_t kf[8][2];
#pragma unroll
            for (int jp = 0; jp < 4; jp++) {
                int nrow = jp * 16 + ((lane >> 4) << 3) + (lane & 7);
                int bk   = kof + (((lane >> 3) & 1) << 3);
                uint32_t bd = stage + (uint32_t)(nrow * AT_STRIDE + bk) * 2;
                ldmatrix_x4(kf[jp*2][0], kf[jp*2][1], kf[jp*2+1][0], kf[jp*2+1][1], bd);
            }
#pragma unroll
            for (int j = 0; j < 8; j++)
                mma_f16(s[j][0], s[j][1], s[j][2], s[j][3],
                        qf[ks][0], qf[ks][1], qf[ks][2], qf[ks][3],
                        kf[j][0], kf[j][1]);
        }

        // ---- online softmax ----
        float rm0 = -1e30f, rm1 = -1e30f;
#pragma unroll
        for (int j = 0; j < 8; j++) {
            rm0 = fmaxf(rm0, fmaxf(s[j][0], s[j][1]));
            rm1 = fmaxf(rm1, fmaxf(s[j][2], s[j][3]));
        }
        rm0 = fmaxf(rm0, __shfl_xor_sync(0xffffffffu, rm0, 1));
        rm0 = fmaxf(rm0, __shfl_xor_sync(0xffffffffu, rm0, 2));
        rm1 = fmaxf(rm1, __shfl_xor_sync(0xffffffffu, rm1, 1));
        rm1 = fmaxf(rm1, __shfl_xor_sync(0xffffffffu, rm1, 2));

        float nm0 = fmaxf(m0, rm0), nm1 = fmaxf(m1, rm1);
        float a0 = __expf(m0 - nm0), a1 = __expf(m1 - nm1);

        float rs0 = 0.f, rs1 = 0.f;
#pragma unroll
        for (int j = 0; j < 8; j++) {
            s[j][0] = __expf(s[j][0] - nm0);
            s[j][1] = __expf(s[j][1] - nm0);
            s[j][2] = __expf(s[j][2] - nm1);
            s[j][3] = __expf(s[j][3] - nm1);
            rs0 += s[j][0] + s[j][1];
            rs1 += s[j][2] + s[j][3];
        }
        rs0 += __shfl_xor_sync(0xffffffffu, rs0, 1);
        rs0 += __shfl_xor_sync(0xffffffffu, rs0, 2);
        rs1 += __shfl_xor_sync(0xffffffffu, rs1, 1);
        rs1 += __shfl_xor_sync(0xffffffffu, rs1, 2);

        l0 = l0 * a0 + rs0;  m0 = nm0;
        l1 = l1 * a1 + rs1;  m1 = nm1;

#pragma unroll
        for (int j = 0; j < 8; j++) {
            o[j][0] *= a0; o[j][1] *= a0;
            o[j][2] *= a1; o[j][3] *= a1;
        }

        // ---- O += P @ V (single fp16 P) ----
#pragma unroll
        for (int kk = 0; kk < 4; kk++) {
            uint32_t ph0 = pack_h2(s[2*kk][0],   s[2*kk][1]);
            uint32_t ph1 = pack_h2(s[2*kk][2],   s[2*kk][3]);
            uint32_t ph2 = pack_h2(s[2*kk+1][0], s[2*kk+1][1]);
            uint32_t ph3 = pack_h2(s[2*kk+1][2], s[2*kk+1][3]);
#pragma unroll
            for (int jp = 0; jp < 4; jp++) {
                int vrow = kk * 16 + (((lane >> 3) & 1) << 3) + (lane & 7);
                int vcol = jp * 16 + ((lane >> 4) << 3);
                uint32_t vd = stage + AT_TILE + (uint32_t)(vrow * AT_STRIDE + vcol) * 2;
                uint32_t v0, v1, v2, v3;
                ldmatrix_x4_trans(v0, v1, v2, v3, vd);
                mma_f16(o[jp*2][0],   o[jp*2][1],   o[jp*2][2],   o[jp*2][3],
                        ph0, ph1, ph2, ph3, v0, v1);
                mma_f16(o[jp*2+1][0], o[jp*2+1][1], o[jp*2+1][2], o[jp*2+1][3],
                        ph0, ph1, ph2, ph3, v2, v3);
            }
        }
        __syncthreads();
    }

    // ---- normalize + fp16 write for out-GEMM ----
    float inv0 = 1.f / l0, inv1 = 1.f / l1;
    const int orow = b * L_ + q0 + wid * 16 + (lane >> 2);
#pragma unroll
    for (int j = 0; j < 8; j++) {
        int col = basecol + j * 8 + (lane & 3) * 2;
        *(__half2*)(a16 + (size_t)orow * E_ + col) =
            __floats2half2_rn(o[j][0] * inv0, o[j][1] * inv0);
        *(__half2*)(a16 + (size_t)(orow + 8) * E_ + col) =
            __floats2half2_rn(o[j][2] * inv1, o[j][3] * inv1);
    }
}

// ---------------------------------------------------------------------------
extern "C" void kernel_launch(void* const* d_in, const int* in_sizes, int n_in,
                              void* d_out, int out_size)
{
    const float* x    = (const float*)d_in[0];
    const float* Wqkv = (const float*)d_in[1];
    const float* bqkv = (const float*)d_in[2];
    const float* Wout = (const float*)d_in[3];
    const float* bout = (const float*)d_in[4];
    float* out = (float*)d_out;

    __half *x16, *wq16, *wo16, *q16, *k16, *v16, *a16;
    cudaGetSymbolAddress((void**)&x16, g_x16);
    cudaGetSymbolAddress((void**)&wq16, g_wqkv16);
    cudaGetSymbolAddress((void**)&wo16, g_wo16);
    cudaGetSymbolAddress((void**)&q16, g_q16);
    cudaGetSymbolAddress((void**)&k16, g_k16);
    cudaGetSymbolAddress((void**)&v16, g_v16);
    cudaGetSymbolAddress((void**)&a16, g_a16);

    static int attr_done = 0;
    if (!attr_done) {
        cudaFuncSetAttribute((const void*)gemm_tc<0>,
                             cudaFuncAttributeMaxDynamicSharedMemorySize, GEMM_SMEM);
        cudaFuncSetAttribute((const void*)gemm_tc<1>,
                             cudaFuncAttributeMaxDynamicSharedMemorySize, GEMM_SMEM);
        cudaFuncSetAttribute(attention_tc,
                             cudaFuncAttributeMaxDynamicSharedMemorySize, ATTN_SMEM);
        attr_done = 1;
    }

    // 0) fused prepass: fp32 -> fp16 (x, Wqkv, Wout)
    conv_all<<<(NALL4 + 255) / 256, 256>>>(
        (const float4*)x, (const float4*)Wqkv, (const float4*)Wout,
        (__half2*)x16, (__half2*)wq16, (__half2*)wo16);

    // 1) QKV projection -> fp16 attention operands
    gemm_tc<1><<<dim3(3 * E_ / 128, M_ / 128), 256, GEMM_SMEM>>>(
        x16, wq16, bqkv, nullptr, q16, k16, v16, M_, 3 * E_, E_);

    // 2) attention -> fp16 attn output
    attention_tc<<<dim3(L_ / 128, H_, B_), 256, ATTN_SMEM>>>(
        q16, k16, v16, a16);

    // 3) out projection (fp32 epilogue)
    gemm_tc<0><<<dim3(E_ / 128, M_ / 128), 256, GEMM_SMEM>>>(
        a16, wo16, bout, out, nullptr, nullptr, nullptr, M_, E_, E_);
}

// round 15
// speedup vs baseline: 1.1073x; 1.1073x over previous
#include <cuda_runtime.h>
#include <cuda_bf16.h>
#include <cuda_fp16.h>
#include <math.h>
#include <stdint.h>

#define B_  2
#define L_  2048
#define E_  1024
#define H_  16
#define HD_ 64
#define M_  (B_ * L_)   // 4096

// ---------------------------------------------------------------------------
// Scratch (fp16 world)
// ---------------------------------------------------------------------------
__device__ __align__(16) __half g_x16[M_ * E_];
__device__ __align__(16) __half g_wqkv16[3 * E_ * E_];
__device__ __align__(16) __half g_wo16[E_ * E_];
__device__ __align__(16) __half g_q16[M_ * E_];
__device__ __align__(16) __half g_k16[M_ * E_];
__device__ __align__(16) __half g_v16[M_ * E_];
__device__ __align__(16) __half g_a16[M_ * E_];

// ---------------------------------------------------------------------------
// helpers
// ---------------------------------------------------------------------------
__device__ __forceinline__ uint32_t smem_to_u32(const void* p) {
    uint32_t a;
    asm("{ .reg .u64 t; cvta.to.shared.u64 t, %1; cvt.u32.u64 %0, t; }" : "=r"(a) : "l"(p));
    return a;
}
__device__ __forceinline__ void cp_async16(uint32_t dst, const void* src) {
    asm volatile("cp.async.cg.shared.global [%0], [%1], 16;" :: "r"(dst), "l"(src));
}
#define CP_COMMIT() asm volatile("cp.async.commit_group;")
#define CP_WAIT2()  asm volatile("cp.async.wait_group 2;")
#define CP_WAIT1()  asm volatile("cp.async.wait_group 1;")
#define CP_WAIT0()  asm volatile("cp.async.wait_group 0;")

__device__ __forceinline__ void ldmatrix_x4(
    uint32_t& r0, uint32_t& r1, uint32_t& r2, uint32_t& r3, uint32_t addr)
{
    asm volatile("ldmatrix.sync.aligned.m8n8.x4.shared.b16 {%0,%1,%2,%3}, [%4];"
        : "=r"(r0), "=r"(r1), "=r"(r2), "=r"(r3) : "r"(addr));
}
__device__ __forceinline__ void ldmatrix_x4_trans(
    uint32_t& r0, uint32_t& r1, uint32_t& r2, uint32_t& r3, uint32_t addr)
{
    asm volatile("ldmatrix.sync.aligned.m8n8.x4.trans.shared.b16 {%0,%1,%2,%3}, [%4];"
        : "=r"(r0), "=r"(r1), "=r"(r2), "=r"(r3) : "r"(addr));
}
__device__ __forceinline__ void mma_f16(
    float& c0, float& c1, float& c2, float& c3,
    uint32_t a0, uint32_t a1, uint32_t a2, uint32_t a3, uint32_t b0, uint32_t b1)
{
    asm volatile(
        "mma.sync.aligned.m16n8k16.row.col.f32.f16.f16.f32 "
        "{%0,%1,%2,%3}, {%4,%5,%6,%7}, {%8,%9}, {%0,%1,%2,%3};"
        : "+f"(c0), "+f"(c1), "+f"(c2), "+f"(c3)
        : "r"(a0), "r"(a1), "r"(a2), "r"(a3), "r"(b0), "r"(b1));
}
__device__ __forceinline__ uint32_t pack_h2(float a, float b) {
    __half2 p = __floats2half2_rn(a, b);
    return *(uint32_t*)&p;
}

// ---------------------------------------------------------------------------
// Fused prepass: fp32 -> fp16 for x, Wqkv, Wout in one launch
// ---------------------------------------------------------------------------
#define NX4  (M_ * E_ / 4)
#define NWQ4 (3 * E_ * E_ / 4)
#define NWO4 (E_ * E_ / 4)
#define NALL4 (NX4 + NWQ4 + NWO4)

__global__ void conv_all(const float4* __restrict__ x,
                         const float4* __restrict__ wq,
                         const float4* __restrict__ wo,
                         __half2* __restrict__ x16,
                         __half2* __restrict__ wq16,
                         __half2* __restrict__ wo16)
{
    int i = blockIdx.x * blockDim.x + threadIdx.x;
    if (i >= NALL4) return;
    const float4* src;
    __half2* dst;
    int j;
    if (i < NX4)             { src = x;  dst = x16;  j = i; }
    else if (i < NX4 + NWQ4) { src = wq; dst = wq16; j = i - NX4; }
    else                     { src = wo; dst = wo16; j = i - NX4 - NWQ4; }
    float4 t = src[j];
    dst[2*j]   = __floats2half2_rn(t.x, t.y);
    dst[2*j+1] = __floats2half2_rn(t.z, t.w);
}

// ---------------------------------------------------------------------------
// GEMM: C = A16 @ W16^T (+bias), 1 fp16 MMA per atom. BK=32.
// 4-stage pipeline, loads issued 2 ahead -> single __syncthreads per iter.
// BM=128, BN=128; 256 threads, 8 warps (warp tile 64x32). stride-40 rows.
// ---------------------------------------------------------------------------
#define GT_STRIDE 40
#define GT_TILE   (128 * GT_STRIDE * 2)   // 10240 B
#define GT_STAGE  (2 * GT_TILE)           // 20480 B (A, W)
#define GEMM_SMEM (4 * GT_STAGE)          // 81920 B

template<int EPI>
__global__ __launch_bounds__(256, 2) void gemm_tc(
    const __half* __restrict__ A16, const __half* __restrict__ W16,
    const float* __restrict__ bias, float* __restrict__ Cf,
    __half* __restrict__ q16, __half* __restrict__ k16, __half* __restrict__ v16,
    int M, int N, int K)
{
    extern __shared__ char smg[];
    const uint32_t sbase = smem_to_u32(smg);

    const int bm   = blockIdx.y * 128;
    const int bn   = blockIdx.x * 128;
    const int tid  = threadIdx.x;
    const int wid  = tid >> 5;
    const int lane = tid & 31;
    const int wm   = wid >> 2;
    const int wn   = wid & 3;

    float c[4][4][4];
#pragma unroll
    for (int i = 0; i < 4; i++)
#pragma unroll
        for (int j = 0; j < 4; j++)
#pragma unroll
            for (int r = 0; r < 4; r++) c[i][j][r] = 0.f;

    auto load_stage = [&](int s, int k0) {
        const uint32_t base = sbase + s * GT_STAGE;
        const __half* srcA = A16 + (size_t)bm * K + k0;
        const __half* srcW = W16 + (size_t)bn * K + k0;
#pragma unroll
        for (int i = 0; i < 2; i++) {
            int chunk = tid * 2 + i;
            int row   = chunk >> 2;
            int cc    = chunk & 3;
            uint32_t doff = row * (GT_STRIDE * 2) + cc * 16;
            cp_async16(base + doff,           srcA + (size_t)row * K + cc * 8);
            cp_async16(base + GT_TILE + doff, srcW + (size_t)row * K + cc * 8);
        }
    };

    const int niter = K / 32;     // 32
    load_stage(0, 0);
    CP_COMMIT();
    load_stage(1, 32);
    CP_COMMIT();

    for (int it = 0; it < niter; it++) {
        if (it + 2 < niter) { load_stage((it + 2) & 3, (it + 2) * 32); CP_COMMIT(); CP_WAIT2(); }
        else if (it + 1 < niter) { CP_WAIT1(); }
        else                     { CP_WAIT0(); }
        __syncthreads();   // single barrier: also separates iter it-2 reads from iter it writes

        const uint32_t stage = sbase + (it & 3) * GT_STAGE;
#pragma unroll
        for (int ks = 0; ks < 2; ks++) {
            const int kof = ks * 16;
            uint32_t af[4][4], bfr[4][2];
#pragma unroll
            for (int i = 0; i < 4; i++) {
                int m0 = wm * 64 + i * 16;
                uint32_t ad = stage +
                    (uint32_t)((m0 + (lane & 15)) * GT_STRIDE + kof + (lane >> 4) * 8) * 2;
                ldmatrix_x4(af[i][0], af[i][1], af[i][2], af[i][3], ad);
            }
#pragma unroll
            for (int jp = 0; jp < 2; jp++) {
                int n0 = wn * 32 + jp * 16;
                int nrow = n0 + ((lane >> 4) << 3) + (lane & 7);
                int bk   = kof + (((lane >> 3) & 1) << 3);
                uint32_t bd = stage + GT_TILE + (uint32_t)(nrow * GT_STRIDE + bk) * 2;
                ldmatrix_x4(bfr[jp*2][0], bfr[jp*2][1], bfr[jp*2+1][0], bfr[jp*2+1][1], bd);
            }
#pragma unroll
            for (int i = 0; i < 4; i++)
#pragma unroll
                for (int j = 0; j < 4; j++)
                    mma_f16(c[i][j][0], c[i][j][1], c[i][j][2], c[i][j][3],
                            af[i][0], af[i][1], af[i][2], af[i][3],
                            bfr[j][0], bfr[j][1]);
        }
        // no trailing __syncthreads: next write target was last read 2 iters ago
    }

    // ---- epilogue ----
    const int g4 = lane >> 2;
    const int t4 = lane & 3;
    if (EPI == 0) {
#pragma unroll
        for (int i = 0; i < 4; i++) {
            int row0 = bm + wm * 64 + i * 16 + g4;
#pragma unroll
            for (int j = 0; j < 4; j++) {
                int col = bn + wn * 32 + j * 8 + t4 * 2;
                float bx = bias[col], by = bias[col + 1];
                *(float2*)(Cf + (size_t)row0 * N + col) =
                    make_float2(c[i][j][0] + bx, c[i][j][1] + by);
                *(float2*)(Cf + (size_t)(row0 + 8) * N + col) =
                    make_float2(c[i][j][2] + bx, c[i][j][3] + by);
            }
        }
    } else {
        const int seg     = bn >> 10;          // 0=Q, 1=K, 2=V
        const int segbase = bn & 1023;
#pragma unroll
        for (int i = 0; i < 4; i++) {
            int row0 = bm + wm * 64 + i * 16 + g4;
#pragma unroll
            for (int j = 0; j < 4; j++) {
                int colg = bn + wn * 32 + j * 8 + t4 * 2;
                int cols = segbase + wn * 32 + j * 8 + t4 * 2;
                float bx = bias[colg], by = bias[colg + 1];
                float v0 = c[i][j][0] + bx, v1 = c[i][j][1] + by;
                float v2 = c[i][j][2] + bx, v3 = c[i][j][3] + by;
                size_t i0 = (size_t)row0 * E_ + cols;
                size_t i1 = (size_t)(row0 + 8) * E_ + cols;
                if (seg == 0) {
                    *(__half2*)(q16 + i0) = __floats2half2_rn(v0 * 0.125f, v1 * 0.125f);
                    *(__half2*)(q16 + i1) = __floats2half2_rn(v2 * 0.125f, v3 * 0.125f);
                } else if (seg == 1) {
                    *(__half2*)(k16 + i0) = __floats2half2_rn(v0, v1);
                    *(__half2*)(k16 + i1) = __floats2half2_rn(v2, v3);
                } else {
                    *(__half2*)(v16 + i0) = __floats2half2_rn(v0, v1);
                    *(__half2*)(v16 + i1) = __floats2half2_rn(v2, v3);
                }
            }
        }
    }
}

// ---------------------------------------------------------------------------
// Flash attention: S = Q16 @ K16^T (1 mma); O += P16 @ V16 (1 mma).
// 4-stage cp.async pipeline, 2 ahead, single barrier per k-tile.
// ---------------------------------------------------------------------------
#define AT_STRIDE 72
#define AT_TILE   (64 * AT_STRIDE * 2)     // 9216
#define AT_STAGE  (2 * AT_TILE)            // 18432 (K16, V16)
#define ATTN_SMEM (4 * AT_STAGE)           // 73728

__global__ __launch_bounds__(256, 2) void attention_tc(
    const __half* __restrict__ q16,
    const __half* __restrict__ k16, const __half* __restrict__ v16,
    __half* __restrict__ a16)
{
    extern __shared__ char sma[];
    const uint32_t sbase = smem_to_u32(sma);

    const int q0   = blockIdx.x * 128;
    const int h    = blockIdx.y;
    const int b    = blockIdx.z;
    const int tid  = threadIdx.x;
    const int wid  = tid >> 5;
    const int lane = tid & 31;
    const int basecol = h * HD_;

    // ---- Q fragments directly from global (ldmatrix A-frag layout) ----
    uint32_t qf[4][4];
    {
        const int r0 = b * L_ + q0 + wid * 16 + (lane >> 2);
        const int c0 = basecol + (lane & 3) * 2;
#pragma unroll
        for (int ks = 0; ks < 4; ks++) {
            size_t i00 = (size_t)r0 * E_ + c0 + ks * 16;
            qf[ks][0] = *(const uint32_t*)(q16 + i00);
            qf[ks][1] = *(const uint32_t*)(q16 + i00 + 8 * E_);
            qf[ks][2] = *(const uint32_t*)(q16 + i00 + 8);
            qf[ks][3] = *(const uint32_t*)(q16 + i00 + 8 * E_ + 8);
        }
    }

    auto load_kv = [&](int s, int kt) {
        const uint32_t base = sbase + s * AT_STAGE;
        const int rowg = b * L_ + kt;
#pragma unroll
        for (int i = 0; i < 2; i++) {
            int chunk = tid * 2 + i;        // 0..511
            int row   = chunk >> 3;
            int cc    = chunk & 7;
            size_t src = (size_t)(rowg + row) * E_ + basecol + cc * 8;
            uint32_t doff = row * (AT_STRIDE * 2) + cc * 16;
            cp_async16(base + doff,           k16 + src);
            cp_async16(base + AT_TILE + doff, v16 + src);
        }
    };

    const int NTILE = L_ / 64;   // 32
    load_kv(0, 0);
    CP_COMMIT();
    load_kv(1, 64);
    CP_COMMIT();

    float o[8][4];
#pragma unroll
    for (int j = 0; j < 8; j++)
#pragma unroll
        for (int r = 0; r < 4; r++) o[j][r] = 0.f;
    float m0 = -1e30f, m1 = -1e30f, l0 = 0.f, l1 = 0.f;

    for (int it = 0; it < NTILE; it++) {
        if (it + 2 < NTILE) { load_kv((it + 2) & 3, (it + 2) * 64); CP_COMMIT(); CP_WAIT2(); }
        else if (it + 1 < NTILE) { CP_WAIT1(); }
        else                     { CP_WAIT0(); }
        __syncthreads();   // single barrier per tile

        const uint32_t stage = sbase + (it & 3) * AT_STAGE;

        // ---- S = Q @ K^T, fp16 ----
        float s[8][4];
#pragma unroll
        for (int j = 0; j < 8; j++)
#pragma unroll
            for (int r = 0; r < 4; r++) s[j][r] = 0.f;

#pragma unroll
        for (int ks = 0; ks < 4; ks++) {
            const int kof = ks * 16;
            uint32_t kf[8][2];
#pragma unroll
            for (int jp = 0; jp < 4; jp++) {
                int nrow = jp * 16 + ((lane >> 4) << 3) + (lane & 7);
                int bk   = kof + (((lane >> 3) & 1) << 3);
                uint32_t bd = stage + (uint32_t)(nrow * AT_STRIDE + bk) * 2;
                ldmatrix_x4(kf[jp*2][0], kf[jp*2][1], kf[jp*2+1][0], kf[jp*2+1][1], bd);
            }
#pragma unroll
            for (int j = 0; j < 8; j++)
                mma_f16(s[j][0], s[j][1], s[j][2], s[j][3],
                        qf[ks][0], qf[ks][1], qf[ks][2], qf[ks][3],
                        kf[j][0], kf[j][1]);
        }

        // ---- online softmax ----
        float rm0 = -1e30f, rm1 = -1e30f;
#pragma unroll
        for (int j = 0; j < 8; j++) {
            rm0 = fmaxf(rm0, fmaxf(s[j][0], s[j][1]));
            rm1 = fmaxf(rm1, fmaxf(s[j][2], s[j][3]));
        }
        rm0 = fmaxf(rm0, __shfl_xor_sync(0xffffffffu, rm0, 1));
        rm0 = fmaxf(rm0, __shfl_xor_sync(0xffffffffu, rm0, 2));
        rm1 = fmaxf(rm1, __shfl_xor_sync(0xffffffffu, rm1, 1));
        rm1 = fmaxf(rm1, __shfl_xor_sync(0xffffffffu, rm1, 2));

        float nm0 = fmaxf(m0, rm0), nm1 = fmaxf(m1, rm1);
        float a0 = __expf(m0 - nm0), a1 = __expf(m1 - nm1);

        float rs0 = 0.f, rs1 = 0.f;
#pragma unroll
        for (int j = 0; j < 8; j++) {
            s[j][0] = __expf(s[j][0] - nm0);
            s[j][1] = __expf(s[j][1] - nm0);
            s[j][2] = __expf(s[j][2] - nm1);
            s[j][3] = __expf(s[j][3] - nm1);
            rs0 += s[j][0] + s[j][1];
            rs1 += s[j][2] + s[j][3];
        }
        rs0 += __shfl_xor_sync(0xffffffffu, rs0, 1);
        rs0 += __shfl_xor_sync(0xffffffffu, rs0, 2);
        rs1 += __shfl_xor_sync(0xffffffffu, rs1, 1);
        rs1 += __shfl_xor_sync(0xffffffffu, rs1, 2);

        l0 = l0 * a0 + rs0;  m0 = nm0;
        l1 = l1 * a1 + rs1;  m1 = nm1;

#pragma unroll
        for (int j = 0; j < 8; j++) {
            o[j][0] *= a0; o[j][1] *= a0;
            o[j][2] *= a1; o[j][3] *= a1;
        }

        // ---- O += P @ V (single fp16 P) ----
#pragma unroll
        for (int kk = 0; kk < 4; kk++) {
            uint32_t ph0 = pack_h2(s[2*kk][0],   s[2*kk][1]);
            uint32_t ph1 = pack_h2(s[2*kk][2],   s[2*kk][3]);
            uint32_t ph2 = pack_h2(s[2*kk+1][0], s[2*kk+1][1]);
            uint32_t ph3 = pack_h2(s[2*kk+1][2], s[2*kk+1][3]);
#pragma unroll
            for (int jp = 0; jp < 4; jp++) {
                int vrow = kk * 16 + (((lane >> 3) & 1) << 3) + (lane & 7);
                int vcol = jp * 16 + ((lane >> 4) << 3);
                uint32_t vd = stage + AT_TILE + (uint32_t)(vrow * AT_STRIDE + vcol) * 2;
                uint32_t v0, v1, v2, v3;
                ldmatrix_x4_trans(v0, v1, v2, v3, vd);
                mma_f16(o[jp*2][0],   o[jp*2][1],   o[jp*2][2],   o[jp*2][3],
                        ph0, ph1, ph2, ph3, v0, v1);
                mma_f16(o[jp*2+1][0], o[jp*2+1][1], o[jp*2+1][2], o[jp*2+1][3],
                        ph0, ph1, ph2, ph3, v2, v3);
            }
        }
        // no trailing __syncthreads
    }

    // ---- normalize + fp16 write for out-GEMM ----
    float inv0 = 1.f / l0, inv1 = 1.f / l1;
    const int orow = b * L_ + q0 + wid * 16 + (lane >> 2);
#pragma unroll
    for (int j = 0; j < 8; j++) {
        int col = basecol + j * 8 + (lane & 3) * 2;
        *(__half2*)(a16 + (size_t)orow * E_ + col) =
            __floats2half2_rn(o[j][0] * inv0, o[j][1] * inv0);
        *(__half2*)(a16 + (size_t)(orow + 8) * E_ + col) =
            __floats2half2_rn(o[j][2] * inv1, o[j][3] * inv1);
    }
}

// ---------------------------------------------------------------------------
extern "C" void kernel_launch(void* const* d_in, const int* in_sizes, int n_in,
                              void* d_out, int out_size)
{
    const float* x    = (const float*)d_in[0];
    const float* Wqkv = (const float*)d_in[1];
    const float* bqkv = (const float*)d_in[2];
    const float* Wout = (const float*)d_in[3];
    const float* bout = (const float*)d_in[4];
    float* out = (float*)d_out;

    __half *x16, *wq16, *wo16, *q16, *k16, *v16, *a16;
    cudaGetSymbolAddress((void**)&x16, g_x16);
    cudaGetSymbolAddress((void**)&wq16, g_wqkv16);
    cudaGetSymbolAddress((void**)&wo16, g_wo16);
    cudaGetSymbolAddress((void**)&q16, g_q16);
    cudaGetSymbolAddress((void**)&k16, g_k16);
    cudaGetSymbolAddress((void**)&v16, g_v16);
    cudaGetSymbolAddress((void**)&a16, g_a16);

    static int attr_done = 0;
    if (!attr_done) {
        cudaFuncSetAttribute((const void*)gemm_tc<0>,
                             cudaFuncAttributeMaxDynamicSharedMemorySize, GEMM_SMEM);
        cudaFuncSetAttribute((const void*)gemm_tc<1>,
                             cudaFuncAttributeMaxDynamicSharedMemorySize, GEMM_SMEM);
        cudaFuncSetAttribute(attention_tc,
                             cudaFuncAttributeMaxDynamicSharedMemorySize, ATTN_SMEM);
        attr_done = 1;
    }

    // 0) fused prepass: fp32 -> fp16 (x, Wqkv, Wout)
    conv_all<<<(NALL4 + 255) / 256, 256>>>(
        (const float4*)x, (const float4*)Wqkv, (const float4*)Wout,
        (__half2*)x16, (__half2*)wq16, (__half2*)wo16);

    // 1) QKV projection -> fp16 attention operands
    gemm_tc<1><<<dim3(3 * E_ / 128, M_ / 128), 256, GEMM_SMEM>>>(
        x16, wq16, bqkv, nullptr, q16, k16, v16, M_, 3 * E_, E_);

    // 2) attention -> fp16 attn output
    attention_tc<<<dim3(L_ / 128, H_, B_), 256, ATTN_SMEM>>>(
        q16, k16, v16, a16);

    // 3) out projection (fp32 epilogue)
    gemm_tc<0><<<dim3(E_ / 128, M_ / 128), 256, GEMM_SMEM>>>(
        a16, wo16, bout, out, nullptr, nullptr, nullptr, M_, E_, E_);
}

// round 16
// speedup vs baseline: 1.1661x; 1.0531x over previous
#include <cuda_runtime.h>
#include <cuda_bf16.h>
#include <cuda_fp16.h>
#include <math.h>
#include <stdint.h>

#define B_  2
#define L_  2048
#define E_  1024
#define H_  16
#define HD_ 64
#define M_  (B_ * L_)   // 4096

// ---------------------------------------------------------------------------
// Scratch (fp16 world)
// ---------------------------------------------------------------------------
__device__ __align__(16) __half g_x16[M_ * E_];
__device__ __align__(16) __half g_wqkv16[3 * E_ * E_];
__device__ __align__(16) __half g_wo16[E_ * E_];
__device__ __align__(16) __half g_q16[M_ * E_];
__device__ __align__(16) __half g_k16[M_ * E_];
__device__ __align__(16) __half g_v16[M_ * E_];
__device__ __align__(16) __half g_a16[M_ * E_];

// ---------------------------------------------------------------------------
// helpers
// ---------------------------------------------------------------------------
__device__ __forceinline__ uint32_t smem_to_u32(const void* p) {
    uint32_t a;
    asm("{ .reg .u64 t; cvta.to.shared.u64 t, %1; cvt.u32.u64 %0, t; }" : "=r"(a) : "l"(p));
    return a;
}
__device__ __forceinline__ void cp_async16(uint32_t dst, const void* src) {
    asm volatile("cp.async.cg.shared.global [%0], [%1], 16;" :: "r"(dst), "l"(src));
}
#define CP_COMMIT() asm volatile("cp.async.commit_group;")
#define CP_WAIT2()  asm volatile("cp.async.wait_group 2;")
#define CP_WAIT1()  asm volatile("cp.async.wait_group 1;")
#define CP_WAIT0()  asm volatile("cp.async.wait_group 0;")

__device__ __forceinline__ void ldmatrix_x4(
    uint32_t& r0, uint32_t& r1, uint32_t& r2, uint32_t& r3, uint32_t addr)
{
    asm volatile("ldmatrix.sync.aligned.m8n8.x4.shared.b16 {%0,%1,%2,%3}, [%4];"
        : "=r"(r0), "=r"(r1), "=r"(r2), "=r"(r3) : "r"(addr));
}
__device__ __forceinline__ void ldmatrix_x4_trans(
    uint32_t& r0, uint32_t& r1, uint32_t& r2, uint32_t& r3, uint32_t addr)
{
    asm volatile("ldmatrix.sync.aligned.m8n8.x4.trans.shared.b16 {%0,%1,%2,%3}, [%4];"
        : "=r"(r0), "=r"(r1), "=r"(r2), "=r"(r3) : "r"(addr));
}
__device__ __forceinline__ void mma_f16(
    float& c0, float& c1, float& c2, float& c3,
    uint32_t a0, uint32_t a1, uint32_t a2, uint32_t a3, uint32_t b0, uint32_t b1)
{
    asm volatile(
        "mma.sync.aligned.m16n8k16.row.col.f32.f16.f16.f32 "
        "{%0,%1,%2,%3}, {%4,%5,%6,%7}, {%8,%9}, {%0,%1,%2,%3};"
        : "+f"(c0), "+f"(c1), "+f"(c2), "+f"(c3)
        : "r"(a0), "r"(a1), "r"(a2), "r"(a3), "r"(b0), "r"(b1));
}
__device__ __forceinline__ uint32_t pack_h2(float a, float b) {
    __half2 p = __floats2half2_rn(a, b);
    return *(uint32_t*)&p;
}

// ---------------------------------------------------------------------------
// Fused prepass: fp32 -> fp16 for x, Wqkv, Wout in one launch
// ---------------------------------------------------------------------------
#define NX4  (M_ * E_ / 4)
#define NWQ4 (3 * E_ * E_ / 4)
#define NWO4 (E_ * E_ / 4)
#define NALL4 (NX4 + NWQ4 + NWO4)

__global__ void conv_all(const float4* __restrict__ x,
                         const float4* __restrict__ wq,
                         const float4* __restrict__ wo,
                         __half2* __restrict__ x16,
                         __half2* __restrict__ wq16,
                         __half2* __restrict__ wo16)
{
    int i = blockIdx.x * blockDim.x + threadIdx.x;
    if (i >= NALL4) return;
    const float4* src;
    __half2* dst;
    int j;
    if (i < NX4)             { src = x;  dst = x16;  j = i; }
    else if (i < NX4 + NWQ4) { src = wq; dst = wq16; j = i - NX4; }
    else                     { src = wo; dst = wo16; j = i - NX4 - NWQ4; }
    float4 t = src[j];
    dst[2*j]   = __floats2half2_rn(t.x, t.y);
    dst[2*j+1] = __floats2half2_rn(t.z, t.w);
}

// ---------------------------------------------------------------------------
// GEMM: C = A16 @ W16^T (+bias). BM=256, BN=128, BK=32.
// 512 threads / 16 warps (4x4 warp grid; warp tile 64x32).
// 4-stage pipeline, loads 2 ahead, single barrier per iteration.
// ---------------------------------------------------------------------------
#define GT_STRIDE 40
#define GA_TILE  (256 * GT_STRIDE * 2)    // 20480 B
#define GW_TILE  (128 * GT_STRIDE * 2)    // 10240 B
#define GT_STAGE (GA_TILE + GW_TILE)      // 30720 B
#define GEMM_SMEM (4 * GT_STAGE)          // 122880 B

template<int EPI>
__global__ __launch_bounds__(512, 1) void gemm_tc(
    const __half* __restrict__ A16, const __half* __restrict__ W16,
    const float* __restrict__ bias, float* __restrict__ Cf,
    __half* __restrict__ q16, __half* __restrict__ k16, __half* __restrict__ v16,
    int M, int N, int K)
{
    extern __shared__ char smg[];
    const uint32_t sbase = smem_to_u32(smg);

    const int bm   = blockIdx.y * 256;
    const int bn   = blockIdx.x * 128;
    const int tid  = threadIdx.x;
    const int wid  = tid >> 5;
    const int lane = tid & 31;
    const int wm   = wid >> 2;        // 0..3 -> 64-row slab
    const int wn   = wid & 3;         // 0..3 -> 32-col slab

    float c[4][4][4];
#pragma unroll
    for (int i = 0; i < 4; i++)
#pragma unroll
        for (int j = 0; j < 4; j++)
#pragma unroll
            for (int r = 0; r < 4; r++) c[i][j][r] = 0.f;

    auto load_stage = [&](int s, int k0) {
        const uint32_t base = sbase + s * GT_STAGE;
        const __half* srcA = A16 + (size_t)bm * K + k0;
        const __half* srcW = W16 + (size_t)bn * K + k0;
        // A: 256 rows x 4 chunks = 1024 chunks -> 2 per thread
#pragma unroll
        for (int i = 0; i < 2; i++) {
            int chunk = tid * 2 + i;
            int row   = chunk >> 2;
            int cc    = chunk & 3;
            cp_async16(base + row * (GT_STRIDE * 2) + cc * 16,
                       srcA + (size_t)row * K + cc * 8);
        }
        // W: 128 rows x 4 chunks = 512 chunks -> 1 per thread
        {
            int chunk = tid;
            int row   = chunk >> 2;
            int cc    = chunk & 3;
            cp_async16(base + GA_TILE + row * (GT_STRIDE * 2) + cc * 16,
                       srcW + (size_t)row * K + cc * 8);
        }
    };

    const int niter = K / 32;     // 32
    load_stage(0, 0);
    CP_COMMIT();
    load_stage(1, 32);
    CP_COMMIT();

    for (int it = 0; it < niter; it++) {
        if (it + 2 < niter) { load_stage((it + 2) & 3, (it + 2) * 32); CP_COMMIT(); CP_WAIT2(); }
        else if (it + 1 < niter) { CP_WAIT1(); }
        else                     { CP_WAIT0(); }
        __syncthreads();

        const uint32_t stage = sbase + (it & 3) * GT_STAGE;
#pragma unroll
        for (int ks = 0; ks < 2; ks++) {
            const int kof = ks * 16;
            uint32_t af[4][4], bfr[4][2];
#pragma unroll
            for (int i = 0; i < 4; i++) {
                int m0 = wm * 64 + i * 16;
                uint32_t ad = stage +
                    (uint32_t)((m0 + (lane & 15)) * GT_STRIDE + kof + (lane >> 4) * 8) * 2;
                ldmatrix_x4(af[i][0], af[i][1], af[i][2], af[i][3], ad);
            }
#pragma unroll
            for (int jp = 0; jp < 2; jp++) {
                int n0 = wn * 32 + jp * 16;
                int nrow = n0 + ((lane >> 4) << 3) + (lane & 7);
                int bk   = kof + (((lane >> 3) & 1) << 3);
                uint32_t bd = stage + GA_TILE + (uint32_t)(nrow * GT_STRIDE + bk) * 2;
                ldmatrix_x4(bfr[jp*2][0], bfr[jp*2][1], bfr[jp*2+1][0], bfr[jp*2+1][1], bd);
            }
#pragma unroll
            for (int i = 0; i < 4; i++)
#pragma unroll
                for (int j = 0; j < 4; j++)
                    mma_f16(c[i][j][0], c[i][j][1], c[i][j][2], c[i][j][3],
                            af[i][0], af[i][1], af[i][2], af[i][3],
                            bfr[j][0], bfr[j][1]);
        }
    }

    // ---- epilogue ----
    const int g4 = lane >> 2;
    const int t4 = lane & 3;
    if (EPI == 0) {
#pragma unroll
        for (int i = 0; i < 4; i++) {
            int row0 = bm + wm * 64 + i * 16 + g4;
#pragma unroll
            for (int j = 0; j < 4; j++) {
                int col = bn + wn * 32 + j * 8 + t4 * 2;
                float bx = bias[col], by = bias[col + 1];
                *(float2*)(Cf + (size_t)row0 * N + col) =
                    make_float2(c[i][j][0] + bx, c[i][j][1] + by);
                *(float2*)(Cf + (size_t)(row0 + 8) * N + col) =
                    make_float2(c[i][j][2] + bx, c[i][j][3] + by);
            }
        }
    } else {
        const int seg     = bn >> 10;          // 0=Q, 1=K, 2=V
        const int segbase = bn & 1023;
#pragma unroll
        for (int i = 0; i < 4; i++) {
            int row0 = bm + wm * 64 + i * 16 + g4;
#pragma unroll
            for (int j = 0; j < 4; j++) {
                int colg = bn + wn * 32 + j * 8 + t4 * 2;
                int cols = segbase + wn * 32 + j * 8 + t4 * 2;
                float bx = bias[colg], by = bias[colg + 1];
                float v0 = c[i][j][0] + bx, v1 = c[i][j][1] + by;
                float v2 = c[i][j][2] + bx, v3 = c[i][j][3] + by;
                size_t i0 = (size_t)row0 * E_ + cols;
                size_t i1 = (size_t)(row0 + 8) * E_ + cols;
                if (seg == 0) {
                    *(__half2*)(q16 + i0) = __floats2half2_rn(v0 * 0.125f, v1 * 0.125f);
                    *(__half2*)(q16 + i1) = __floats2half2_rn(v2 * 0.125f, v3 * 0.125f);
                } else if (seg == 1) {
                    *(__half2*)(k16 + i0) = __floats2half2_rn(v0, v1);
                    *(__half2*)(k16 + i1) = __floats2half2_rn(v2, v3);
                } else {
                    *(__half2*)(v16 + i0) = __floats2half2_rn(v0, v1);
                    *(__half2*)(v16 + i1) = __floats2half2_rn(v2, v3);
                }
            }
        }
    }
}

// ---------------------------------------------------------------------------
// Flash attention: q-tile 256 rows, 512 threads / 16 warps (16 rows each).
// S = Q16 @ K16^T (1 mma); O += P16 @ V16 (1 mma). K-tiles of 64.
// 4-stage cp.async pipeline, 2 ahead, single barrier per tile.
// ---------------------------------------------------------------------------
#define AT_STRIDE 72
#define AT_TILE   (64 * AT_STRIDE * 2)     // 9216
#define AT_STAGE  (2 * AT_TILE)            // 18432 (K16, V16)
#define ATTN_SMEM (4 * AT_STAGE)           // 73728

__global__ __launch_bounds__(512, 1) void attention_tc(
    const __half* __restrict__ q16,
    const __half* __restrict__ k16, const __half* __restrict__ v16,
    __half* __restrict__ a16)
{
    extern __shared__ char sma[];
    const uint32_t sbase = smem_to_u32(sma);

    const int q0   = blockIdx.x * 256;
    const int h    = blockIdx.y;
    const int b    = blockIdx.z;
    const int tid  = threadIdx.x;
    const int wid  = tid >> 5;       // 0..15
    const int lane = tid & 31;
    const int basecol = h * HD_;

    // ---- Q fragments directly from global (ldmatrix A-frag layout) ----
    uint32_t qf[4][4];
    {
        const int r0 = b * L_ + q0 + wid * 16 + (lane >> 2);
        const int c0 = basecol + (lane & 3) * 2;
#pragma unroll
        for (int ks = 0; ks < 4; ks++) {
            size_t i00 = (size_t)r0 * E_ + c0 + ks * 16;
            qf[ks][0] = *(const uint32_t*)(q16 + i00);
            qf[ks][1] = *(const uint32_t*)(q16 + i00 + 8 * E_);
            qf[ks][2] = *(const uint32_t*)(q16 + i00 + 8);
            qf[ks][3] = *(const uint32_t*)(q16 + i00 + 8 * E_ + 8);
        }
    }

    auto load_kv = [&](int s, int kt) {
        const uint32_t base = sbase + s * AT_STAGE;
        const int rowg = b * L_ + kt;
        // K: 512 chunks, V: 512 chunks -> 1 each per thread
        int row = tid >> 3;
        int cc  = tid & 7;
        size_t src = (size_t)(rowg + row) * E_ + basecol + cc * 8;
        uint32_t doff = row * (AT_STRIDE * 2) + cc * 16;
        cp_async16(base + doff,           k16 + src);
        cp_async16(base + AT_TILE + doff, v16 + src);
    };

    const int NTILE = L_ / 64;   // 32
    load_kv(0, 0);
    CP_COMMIT();
    load_kv(1, 64);
    CP_COMMIT();

    float o[8][4];
#pragma unroll
    for (int j = 0; j < 8; j++)
#pragma unroll
        for (int r = 0; r < 4; r++) o[j][r] = 0.f;
    float m0 = -1e30f, m1 = -1e30f, l0 = 0.f, l1 = 0.f;

    for (int it = 0; it < NTILE; it++) {
        if (it + 2 < NTILE) { load_kv((it + 2) & 3, (it + 2) * 64); CP_COMMIT(); CP_WAIT2(); }
        else if (it + 1 < NTILE) { CP_WAIT1(); }
        else                     { CP_WAIT0(); }
        __syncthreads();

        const uint32_t stage = sbase + (it & 3) * AT_STAGE;

        // ---- S = Q @ K^T, fp16 ----
        float s[8][4];
#pragma unroll
        for (int j = 0; j < 8; j++)
#pragma unroll
            for (int r = 0; r < 4; r++) s[j][r] = 0.f;

#pragma unroll
        for (int ks = 0; ks < 4; ks++) {
            const int kof = ks * 16;
            uint32_t kf[8][2];
#pragma unroll
            for (int jp = 0; jp < 4; jp++) {
                int nrow = jp * 16 + ((lane >> 4) << 3) + (lane & 7);
                int bk   = kof + (((lane >> 3) & 1) << 3);
                uint32_t bd = stage + (uint32_t)(nrow * AT_STRIDE + bk) * 2;
                ldmatrix_x4(kf[jp*2][0], kf[jp*2][1], kf[jp*2+1][0], kf[jp*2+1][1], bd);
            }
#pragma unroll
            for (int j = 0; j < 8; j++)
                mma_f16(s[j][0], s[j][1], s[j][2], s[j][3],
                        qf[ks][0], qf[ks][1], qf[ks][2], qf[ks][3],
                        kf[j][0], kf[j][1]);
        }

        // ---- online softmax ----
        float rm0 = -1e30f, rm1 = -1e30f;
#pragma unroll
        for (int j = 0; j < 8; j++) {
            rm0 = fmaxf(rm0, fmaxf(s[j][0], s[j][1]));
            rm1 = fmaxf(rm1, fmaxf(s[j][2], s[j][3]));
        }
        rm0 = fmaxf(rm0, __shfl_xor_sync(0xffffffffu, rm0, 1));
        rm0 = fmaxf(rm0, __shfl_xor_sync(0xffffffffu, rm0, 2));
        rm1 = fmaxf(rm1, __shfl_xor_sync(0xffffffffu, rm1, 1));
        rm1 = fmaxf(rm1, __shfl_xor_sync(0xffffffffu, rm1, 2));

        float nm0 = fmaxf(m0, rm0), nm1 = fmaxf(m1, rm1);
        float a0 = __expf(m0 - nm0), a1 = __expf(m1 - nm1);

        float rs0 = 0.f, rs1 = 0.f;
#pragma unroll
        for (int j = 0; j < 8; j++) {
            s[j][0] = __expf(s[j][0] - nm0);
            s[j][1] = __expf(s[j][1] - nm0);
            s[j][2] = __expf(s[j][2] - nm1);
            s[j][3] = __expf(s[j][3] - nm1);
            rs0 += s[j][0] + s[j][1];
            rs1 += s[j][2] + s[j][3];
        }
        rs0 += __shfl_xor_sync(0xffffffffu, rs0, 1);
        rs0 += __shfl_xor_sync(0xffffffffu, rs0, 2);
        rs1 += __shfl_xor_sync(0xffffffffu, rs1, 1);
        rs1 += __shfl_xor_sync(0xffffffffu, rs1, 2);

        l0 = l0 * a0 + rs0;  m0 = nm0;
        l1 = l1 * a1 + rs1;  m1 = nm1;

#pragma unroll
        for (int j = 0; j < 8; j++) {
            o[j][0] *= a0; o[j][1] *= a0;
            o[j][2] *= a1; o[j][3] *= a1;
        }

        // ---- O += P @ V (single fp16 P) ----
#pragma unroll
        for (int kk = 0; kk < 4; kk++) {
            uint32_t ph0 = pack_h2(s[2*kk][0],   s[2*kk][1]);
            uint32_t ph1 = pack_h2(s[2*kk][2],   s[2*kk][3]);
            uint32_t ph2 = pack_h2(s[2*kk+1][0], s[2*kk+1][1]);
            uint32_t ph3 = pack_h2(s[2*kk+1][2], s[2*kk+1][3]);
#pragma unroll
            for (int jp = 0; jp < 4; jp++) {
                int vrow = kk * 16 + (((lane >> 3) & 1) << 3) + (lane & 7);
                int vcol = jp * 16 + ((lane >> 4) << 3);
                uint32_t vd = stage + AT_TILE + (uint32_t)(vrow * AT_STRIDE + vcol) * 2;
                uint32_t v0, v1, v2, v3;
                ldmatrix_x4_trans(v0, v1, v2, v3, vd);
                mma_f16(o[jp*2][0],   o[jp*2][1],   o[jp*2][2],   o[jp*2][3],
                        ph0, ph1, ph2, ph3, v0, v1);
                mma_f16(o[jp*2+1][0], o[jp*2+1][1], o[jp*2+1][2], o[jp*2+1][3],
                        ph0, ph1, ph2, ph3, v2, v3);
            }
        }
    }

    // ---- normalize + fp16 write for out-GEMM ----
    float inv0 = 1.f / l0, inv1 = 1.f / l1;
    const int orow = b * L_ + q0 + wid * 16 + (lane >> 2);
#pragma unroll
    for (int j = 0; j < 8; j++) {
        int col = basecol + j * 8 + (lane & 3) * 2;
        *(__half2*)(a16 + (size_t)orow * E_ + col) =
            __floats2half2_rn(o[j][0] * inv0, o[j][1] * inv0);
        *(__half2*)(a16 + (size_t)(orow + 8) * E_ + col) =
            __floats2half2_rn(o[j][2] * inv1, o[j][3] * inv1);
    }
}

// ---------------------------------------------------------------------------
extern "C" void kernel_launch(void* const* d_in, const int* in_sizes, int n_in,
                              void* d_out, int out_size)
{
    const float* x    = (const float*)d_in[0];
    const float* Wqkv = (const float*)d_in[1];
    const float* bqkv = (const float*)d_in[2];
    const float* Wout = (const float*)d_in[3];
    const float* bout = (const float*)d_in[4];
    float* out = (float*)d_out;

    __half *x16, *wq16, *wo16, *q16, *k16, *v16, *a16;
    cudaGetSymbolAddress((void**)&x16, g_x16);
    cudaGetSymbolAddress((void**)&wq16, g_wqkv16);
    cudaGetSymbolAddress((void**)&wo16, g_wo16);
    cudaGetSymbolAddress((void**)&q16, g_q16);
    cudaGetSymbolAddress((void**)&k16, g_k16);
    cudaGetSymbolAddress((void**)&v16, g_v16);
    cudaGetSymbolAddress((void**)&a16, g_a16);

    static int attr_done = 0;
    if (!attr_done) {
        cudaFuncSetAttribute((const void*)gemm_tc<0>,
                             cudaFuncAttributeMaxDynamicSharedMemorySize, GEMM_SMEM);
        cudaFuncSetAttribute((const void*)gemm_tc<1>,
                             cudaFuncAttributeMaxDynamicSharedMemorySize, GEMM_SMEM);
        cudaFuncSetAttribute(attention_tc,
                             cudaFuncAttributeMaxDynamicSharedMemorySize, ATTN_SMEM);
        attr_done = 1;
    }

    // 0) fused prepass: fp32 -> fp16 (x, Wqkv, Wout)
    conv_all<<<(NALL4 + 255) / 256, 256>>>(
        (const float4*)x, (const float4*)Wqkv, (const float4*)Wout,
        (__half2*)x16, (__half2*)wq16, (__half2*)wo16);

    // 1) QKV projection -> fp16 attention operands  (grid 24 x 16)
    gemm_tc<1><<<dim3(3 * E_ / 128, M_ / 256), 512, GEMM_SMEM>>>(
        x16, wq16, bqkv, nullptr, q16, k16, v16, M_, 3 * E_, E_);

    // 2) attention -> fp16 attn output  (grid 8 x 16 x 2)
    attention_tc<<<dim3(L_ / 256, H_, B_), 512, ATTN_SMEM>>>(
        q16, k16, v16, a16);

    // 3) out projection (fp32 epilogue)  (grid 8 x 16)
    gemm_tc<0><<<dim3(E_ / 128, M_ / 256), 512, GEMM_SMEM>>>(
        a16, wo16, bout, out, nullptr, nullptr, nullptr, M_, E_, E_);
}